// round 8
// baseline (speedup 1.0000x reference)
#include <cuda_runtime.h>
#include <math.h>

#define DD    20
#define TPB   128
#define GRID  592           // 4 blocks/SM * 148 SMs
#define ROWS_PER_TILE (TPB * 4)

typedef unsigned long long u64;

// ---------------- packed f32x2 helpers (sm_103a) ----------------
__device__ __forceinline__ u64 pk(float lo, float hi) {
    u64 r; asm("mov.b64 %0, {%1, %2};" : "=l"(r) : "f"(lo), "f"(hi)); return r;
}
__device__ __forceinline__ void upk(u64 v, float& lo, float& hi) {
    asm("mov.b64 {%0, %1}, %2;" : "=f"(lo), "=f"(hi) : "l"(v));
}
__device__ __forceinline__ u64 fma2(u64 a, u64 b, u64 c) {
    u64 d; asm("fma.rn.f32x2 %0, %1, %2, %3;" : "=l"(d) : "l"(a), "l"(b), "l"(c)); return d;
}
__device__ __forceinline__ u64 relu2(u64 v) {
    float a, b; upk(v, a, b);
    return pk(fmaxf(a, 0.0f), fmaxf(b, 0.0f));
}
__device__ __forceinline__ float comp(const float4& q, int c) {
    return c == 0 ? q.x : c == 1 ? q.y : c == 2 ? q.z : q.w;
}

// ---------------- device-global scratch ----------------
__device__ double g_pS[1024];
__device__ double g_pQ[1024];
__device__ unsigned int g_ticket = 0;

// =====================================================================
// fused persistent kernel: 4 rows/thread, j-pair packing, 4 blocks/SM
// =====================================================================
__global__ void __launch_bounds__(TPB, 4)
main_kernel(const float* __restrict__ x,
            const float* __restrict__ W,
            const float* __restrict__ b,
            const float* __restrict__ R,
            float* __restrict__ out,
            int B) {
    __shared__ float sWf[DD * DD];
    __shared__ float sRf[DD * DD];
    __shared__ float sbf[DD];
    // undupped float weight arrays (j-contiguous pairs)
    __shared__ __align__(16) float sM1f[DD * DD];  // M1[k][j]
    __shared__ __align__(16) float sTf[DD * DD];   // T[i][k]: G_ii diag, 2G above, 0 below
    __shared__ __align__(16) float sc1f[DD];       // b@R + 1
    __shared__ __align__(16) float swcsf[DD];      // column sums of W
    __shared__ __align__(16) float su2f[DD];       // 2 * W^T b
    __shared__ double redS[TPB];
    __shared__ double redQ[TPB];
    __shared__ int sIsLast;

    const int tid = threadIdx.x;

    // ---- stage W, R, b ----
    for (int i = tid; i < DD * DD; i += TPB) { sWf[i] = W[i]; sRf[i] = R[i]; }
    if (tid < DD) sbf[tid] = b[tid];
    __syncthreads();

    // ---- fold (once per block) ----
    for (int i = tid; i < DD * DD; i += TPB) {
        int k = i / DD, j = i % DD;
        float m1 = 0.0f, g = 0.0f;
        #pragma unroll
        for (int m = 0; m < DD; m++) {
            m1 = fmaf(sWf[m * DD + k], sRf[m * DD + j], m1);
            g  = fmaf(sWf[m * DD + k], sWf[m * DD + j], g);
        }
        sM1f[i] = m1;
        sTf[i]  = (j > k) ? (2.0f * g) : ((j == k) ? g : 0.0f);
    }
    if (tid < DD) {
        float c = 1.0f, wcs = 0.0f, u = 0.0f;
        #pragma unroll
        for (int m = 0; m < DD; m++) {
            c   = fmaf(sbf[m], sRf[m * DD + tid], c);
            wcs += sWf[m * DD + tid];
            u   = fmaf(sWf[m * DD + tid], sbf[m], u);
        }
        sc1f[tid]  = c;
        swcsf[tid] = wcs;
        su2f[tid]  = 2.0f * u;
    }
    __syncthreads();

    const ulonglong2* sM1v = (const ulonglong2*)sM1f;   // [k*5 + jp2]
    const u64*        sc1v = (const u64*)sc1f;
    const ulonglong2* wcsv = (const ulonglong2*)swcsf;
    const ulonglong2* u2v  = (const ulonglong2*)su2f;

    float sl = 0.0f, ql = 0.0f;
    const long long rowsTotal = (long long)B;

    #pragma unroll 1
    for (long long tile = blockIdx.x; tile * ROWS_PER_TILE < rowsTotal; tile += GRID) {
        long long row0 = tile * ROWS_PER_TILE + (long long)tid * 4;
        if (row0 + 4 <= rowsTotal) {
            const float4* xp = (const float4*)(x + row0 * DD);

            // accumulators: j-pairs per row (80 regs)
            u64 a0[DD/2], a1[DD/2], a2[DD/2], a3[DD/2];
            #pragma unroll
            for (int jp = 0; jp < DD/2; jp++) {
                u64 c = sc1v[jp];
                a0[jp] = c; a1[jp] = c; a2[jp] = c; a3[jp] = c;
            }

            // stream x: load 4 float4 per i-step (no double-buffer: save regs)
            #pragma unroll
            for (int i = 0; i < 5; i++) {
                float4 A0 = xp[i], B0 = xp[5+i], C0 = xp[10+i], D0 = xp[15+i];
                #pragma unroll
                for (int c = 0; c < 4; c++) {
                    const int k = 4 * i + c;
                    float x0 = comp(A0,c), x1 = comp(B0,c), x2 = comp(C0,c), x3 = comp(D0,c);
                    u64 xv0 = pk(x0, x0), xv1 = pk(x1, x1), xv2 = pk(x2, x2), xv3 = pk(x3, x3);
                    #pragma unroll
                    for (int jp2 = 0; jp2 < 5; jp2++) {
                        ulonglong2 w = sM1v[k * 5 + jp2];   // 4 distinct weights
                        a0[2*jp2+0] = fma2(xv0, w.x, a0[2*jp2+0]);
                        a1[2*jp2+0] = fma2(xv1, w.x, a1[2*jp2+0]);
                        a2[2*jp2+0] = fma2(xv2, w.x, a2[2*jp2+0]);
                        a3[2*jp2+0] = fma2(xv3, w.x, a3[2*jp2+0]);
                        a0[2*jp2+1] = fma2(xv0, w.y, a0[2*jp2+1]);
                        a1[2*jp2+1] = fma2(xv1, w.y, a1[2*jp2+1]);
                        a2[2*jp2+1] = fma2(xv2, w.y, a2[2*jp2+1]);
                        a3[2*jp2+1] = fma2(xv3, w.y, a3[2*jp2+1]);
                    }
                }
            }
            #pragma unroll
            for (int jp = 0; jp < DD/2; jp++) {
                a0[jp] = relu2(a0[jp]); a1[jp] = relu2(a1[jp]);
                a2[jp] = relu2(a2[jp]); a3[jp] = relu2(a3[jp]);
            }

            // linear terms: S += wcs.h ; Q += (2 W^T b).h
            u64 s0 = 0ULL, s1 = 0ULL, s2v = 0ULL, s3 = 0ULL;
            u64 q0 = 0ULL, q1 = 0ULL, q2v = 0ULL, q3 = 0ULL;
            #pragma unroll
            for (int jp2 = 0; jp2 < 5; jp2++) {
                ulonglong2 wc = wcsv[jp2];
                ulonglong2 uu = u2v[jp2];
                s0 = fma2(a0[2*jp2+0], wc.x, s0);  s0 = fma2(a0[2*jp2+1], wc.y, s0);
                s1 = fma2(a1[2*jp2+0], wc.x, s1);  s1 = fma2(a1[2*jp2+1], wc.y, s1);
                s2v= fma2(a2[2*jp2+0], wc.x, s2v); s2v= fma2(a2[2*jp2+1], wc.y, s2v);
                s3 = fma2(a3[2*jp2+0], wc.x, s3);  s3 = fma2(a3[2*jp2+1], wc.y, s3);
                q0 = fma2(a0[2*jp2+0], uu.x, q0);  q0 = fma2(a0[2*jp2+1], uu.y, q0);
                q1 = fma2(a1[2*jp2+0], uu.x, q1);  q1 = fma2(a1[2*jp2+1], uu.y, q1);
                q2v= fma2(a2[2*jp2+0], uu.x, q2v); q2v= fma2(a2[2*jp2+1], uu.y, q2v);
                q3 = fma2(a3[2*jp2+0], uu.x, q3);  q3 = fma2(a3[2*jp2+1], uu.y, q3);
            }

            // quadratic: Q += sum_i h_i * (T h)_i, T upper-tri
            float qs0 = 0.0f, qs1 = 0.0f, qs2 = 0.0f, qs3 = 0.0f;
            #pragma unroll
            for (int i = 0; i < DD; i++) {
                const int kp0 = i >> 1;
                const u64* Trow = (const u64*)(sTf + i * DD);
                u64 y0 = 0ULL, y1 = 0ULL, y2 = 0ULL, y3 = 0ULL;
                #pragma unroll
                for (int kp = kp0; kp < DD/2; kp++) {
                    u64 w = Trow[kp];
                    y0 = fma2(a0[kp], w, y0);
                    y1 = fma2(a1[kp], w, y1);
                    y2 = fma2(a2[kp], w, y2);
                    y3 = fma2(a3[kp], w, y3);
                }
                float lo, hi, hl, hh, h;
                upk(y0, lo, hi); upk(a0[kp0], hl, hh); h = (i & 1) ? hh : hl;
                qs0 = fmaf(h, lo + hi, qs0);
                upk(y1, lo, hi); upk(a1[kp0], hl, hh); h = (i & 1) ? hh : hl;
                qs1 = fmaf(h, lo + hi, qs1);
                upk(y2, lo, hi); upk(a2[kp0], hl, hh); h = (i & 1) ? hh : hl;
                qs2 = fmaf(h, lo + hi, qs2);
                upk(y3, lo, hi); upk(a3[kp0], hl, hh); h = (i & 1) ? hh : hl;
                qs3 = fmaf(h, lo + hi, qs3);
            }

            float lo, hi;
            upk(s0, lo, hi); sl += lo + hi;
            upk(s1, lo, hi); sl += lo + hi;
            upk(s2v, lo, hi); sl += lo + hi;
            upk(s3, lo, hi); sl += lo + hi;
            upk(q0, lo, hi); ql += lo + hi + qs0;
            upk(q1, lo, hi); ql += lo + hi + qs1;
            upk(q2v, lo, hi); ql += lo + hi + qs2;
            upk(q3, lo, hi); ql += lo + hi + qs3;
        } else if (row0 < rowsTotal) {
            // scalar tail
            for (long long r = row0; r < rowsTotal && r < row0 + 4; r++) {
                const float* xr = x + r * DD;
                float h[DD];
                #pragma unroll
                for (int j = 0; j < DD; j++) h[j] = sc1f[j];
                for (int k = 0; k < DD; k++) {
                    float xv = xr[k];
                    #pragma unroll
                    for (int j = 0; j < DD; j++) h[j] = fmaf(xv, sM1f[k * DD + j], h[j]);
                }
                #pragma unroll
                for (int j = 0; j < DD; j++) h[j] = fmaxf(h[j], 0.0f);
                #pragma unroll
                for (int k = 0; k < DD; k++) {
                    sl = fmaf(h[k], swcsf[k], sl);
                    ql = fmaf(h[k], su2f[k], ql);
                }
                for (int i = 0; i < DD; i++) {
                    float y = 0.0f;
                    for (int k = i; k < DD; k++) y = fmaf(h[k], sTf[i * DD + k], y);
                    ql = fmaf(h[i], y, ql);
                }
            }
        }
    }

    // ---- deterministic block reduction ----
    redS[tid] = (double)sl;
    redQ[tid] = (double)ql;
    __syncthreads();
    for (int s = TPB / 2; s > 0; s >>= 1) {
        if (tid < s) { redS[tid] += redS[tid + s]; redQ[tid] += redQ[tid + s]; }
        __syncthreads();
    }
    if (tid == 0) {
        g_pS[blockIdx.x] = redS[0];
        g_pQ[blockIdx.x] = redQ[0];
        __threadfence();
        unsigned int t = atomicAdd(&g_ticket, 1u);
        sIsLast = (t == (unsigned int)(GRID - 1)) ? 1 : 0;
    }
    __syncthreads();

    // ---- last block: global reduce + scalar postlude ----
    if (sIsLast) {
        __threadfence();
        double s = 0.0, q = 0.0;
        for (int i = tid; i < GRID; i += TPB) { s += g_pS[i]; q += g_pQ[i]; }
        redS[tid] = s; redQ[tid] = q;
        __syncthreads();
        for (int st = TPB / 2; st > 0; st >>= 1) {
            if (tid < st) { redS[tid] += redS[tid + st]; redQ[tid] += redQ[tid + st]; }
            __syncthreads();
        }
        if (tid == 0) {
            double sb = 0.0, bb = 0.0;
            #pragma unroll
            for (int m = 0; m < DD; m++) { sb += (double)sbf[m]; bb += (double)sbf[m] * (double)sbf[m]; }
            double S = redS[0] + (double)B * sb;
            double Q = redQ[0] + (double)B * bb;
            float n = (float)sqrt(Q);
            int k = 0;
            while (n > 1.0f && k < 300) { n *= 0.5f; k++; }   // exact halvings in fp32
            float mult = (n < 0.8f) ? 10.0f : 1.0f;
            double scale = ldexp(1.0, -k);
            out[0] = (float)(S * scale * (double)mult);
            g_ticket = 0;
        }
    }
}

// ---------------- entry point ----------------
extern "C" void kernel_launch(void* const* d_in, const int* in_sizes, int n_in,
                              void* d_out, int out_size) {
    const float* x = (const float*)d_in[0];
    const float* W = (const float*)d_in[1];
    const float* b = (const float*)d_in[2];
    const float* R = (const float*)d_in[3];
    int B = in_sizes[0] / DD;

    main_kernel<<<GRID, TPB>>>(x, W, b, R, (float*)d_out, B);
}

// round 9
// speedup vs baseline: 1.1608x; 1.1608x over previous
#include <cuda_runtime.h>
#include <math.h>

#define DD    20
#define TPB   128
#define GRID  592           // 4 blocks/SM * 148 SMs
#define ROWS_PER_TILE (TPB * 4)

typedef unsigned long long u64;

// ---------------- packed f32x2 helpers (sm_103a) ----------------
__device__ __forceinline__ u64 pk(float lo, float hi) {
    u64 r; asm("mov.b64 %0, {%1, %2};" : "=l"(r) : "f"(lo), "f"(hi)); return r;
}
__device__ __forceinline__ void upk(u64 v, float& lo, float& hi) {
    asm("mov.b64 {%0, %1}, %2;" : "=f"(lo), "=f"(hi) : "l"(v));
}
__device__ __forceinline__ u64 fma2(u64 a, u64 b, u64 c) {
    u64 d; asm("fma.rn.f32x2 %0, %1, %2, %3;" : "=l"(d) : "l"(a), "l"(b), "l"(c)); return d;
}
__device__ __forceinline__ u64 relu2(u64 v) {
    float a, b; upk(v, a, b);
    return pk(fmaxf(a, 0.0f), fmaxf(b, 0.0f));
}
__device__ __forceinline__ float comp(const float4& q, int c) {
    return c == 0 ? q.x : c == 1 ? q.y : c == 2 ? q.z : q.w;
}

// ---------------- device-global scratch ----------------
__device__ double g_pS[1024];
__device__ double g_pQ[1024];
__device__ unsigned int g_ticket = 0;

// =====================================================================
// fused persistent kernel: 4 rows/thread, j-pair packing,
// x prefetch double-buffer KEPT, capped at 128 regs -> 16 warps/SM
// =====================================================================
__global__ void __launch_bounds__(TPB, 4)
main_kernel(const float* __restrict__ x,
            const float* __restrict__ W,
            const float* __restrict__ b,
            const float* __restrict__ R,
            float* __restrict__ out,
            int B) {
    __shared__ float sWf[DD * DD];
    __shared__ float sRf[DD * DD];
    __shared__ float sbf[DD];
    // undupped float weight arrays (j-contiguous pairs)
    __shared__ __align__(16) float sM1f[DD * DD];  // M1[k][j]
    __shared__ __align__(16) float sTf[DD * DD];   // T[i][k]: G_ii diag, 2G above, 0 below
    __shared__ __align__(16) float sc1f[DD];       // b@R + 1
    __shared__ __align__(16) float swcsf[DD];      // column sums of W
    __shared__ __align__(16) float su2f[DD];       // 2 * W^T b
    __shared__ double redS[TPB];
    __shared__ double redQ[TPB];
    __shared__ int sIsLast;

    const int tid = threadIdx.x;

    // ---- stage W, R, b ----
    for (int i = tid; i < DD * DD; i += TPB) { sWf[i] = W[i]; sRf[i] = R[i]; }
    if (tid < DD) sbf[tid] = b[tid];
    __syncthreads();

    // ---- fold (once per block) ----
    for (int i = tid; i < DD * DD; i += TPB) {
        int k = i / DD, j = i % DD;
        float m1 = 0.0f, g = 0.0f;
        #pragma unroll
        for (int m = 0; m < DD; m++) {
            m1 = fmaf(sWf[m * DD + k], sRf[m * DD + j], m1);
            g  = fmaf(sWf[m * DD + k], sWf[m * DD + j], g);
        }
        sM1f[i] = m1;
        sTf[i]  = (j > k) ? (2.0f * g) : ((j == k) ? g : 0.0f);
    }
    if (tid < DD) {
        float c = 1.0f, wcs = 0.0f, u = 0.0f;
        #pragma unroll
        for (int m = 0; m < DD; m++) {
            c   = fmaf(sbf[m], sRf[m * DD + tid], c);
            wcs += sWf[m * DD + tid];
            u   = fmaf(sWf[m * DD + tid], sbf[m], u);
        }
        sc1f[tid]  = c;
        swcsf[tid] = wcs;
        su2f[tid]  = 2.0f * u;
    }
    __syncthreads();

    const ulonglong2* sM1v = (const ulonglong2*)sM1f;   // [k*5 + jp2]
    const u64*        sc1v = (const u64*)sc1f;
    const ulonglong2* wcsv = (const ulonglong2*)swcsf;
    const ulonglong2* u2v  = (const ulonglong2*)su2f;

    float sl = 0.0f, ql = 0.0f;
    const long long rowsTotal = (long long)B;

    #pragma unroll 1
    for (long long tile = blockIdx.x; tile * ROWS_PER_TILE < rowsTotal; tile += GRID) {
        long long row0 = tile * ROWS_PER_TILE + (long long)tid * 4;
        if (row0 + 4 <= rowsTotal) {
            const float4* xp = (const float4*)(x + row0 * DD);

            // accumulators: j-pairs per row (80 regs)
            u64 a0[DD/2], a1[DD/2], a2[DD/2], a3[DD/2];
            #pragma unroll
            for (int jp = 0; jp < DD/2; jp++) {
                u64 c = sc1v[jp];
                a0[jp] = c; a1[jp] = c; a2[jp] = c; a3[jp] = c;
            }

            // stream x: one float4 per row per i-step, prefetch next step
            float4 A0 = xp[0], B0 = xp[5], C0 = xp[10], D0 = xp[15];
            #pragma unroll
            for (int i = 0; i < 5; i++) {
                float4 A1, B1, C1, D1;
                if (i < 4) { A1 = xp[i+1]; B1 = xp[6+i]; C1 = xp[11+i]; D1 = xp[16+i]; }
                #pragma unroll
                for (int c = 0; c < 4; c++) {
                    const int k = 4 * i + c;
                    float x0 = comp(A0,c), x1 = comp(B0,c), x2 = comp(C0,c), x3 = comp(D0,c);
                    u64 xv0 = pk(x0, x0), xv1 = pk(x1, x1), xv2 = pk(x2, x2), xv3 = pk(x3, x3);
                    #pragma unroll
                    for (int jp2 = 0; jp2 < 5; jp2++) {
                        ulonglong2 w = sM1v[k * 5 + jp2];   // 4 distinct weights
                        a0[2*jp2+0] = fma2(xv0, w.x, a0[2*jp2+0]);
                        a1[2*jp2+0] = fma2(xv1, w.x, a1[2*jp2+0]);
                        a2[2*jp2+0] = fma2(xv2, w.x, a2[2*jp2+0]);
                        a3[2*jp2+0] = fma2(xv3, w.x, a3[2*jp2+0]);
                        a0[2*jp2+1] = fma2(xv0, w.y, a0[2*jp2+1]);
                        a1[2*jp2+1] = fma2(xv1, w.y, a1[2*jp2+1]);
                        a2[2*jp2+1] = fma2(xv2, w.y, a2[2*jp2+1]);
                        a3[2*jp2+1] = fma2(xv3, w.y, a3[2*jp2+1]);
                    }
                }
                A0 = A1; B0 = B1; C0 = C1; D0 = D1;
            }
            #pragma unroll
            for (int jp = 0; jp < DD/2; jp++) {
                a0[jp] = relu2(a0[jp]); a1[jp] = relu2(a1[jp]);
                a2[jp] = relu2(a2[jp]); a3[jp] = relu2(a3[jp]);
            }

            // linear terms: S += wcs.h ; Q += (2 W^T b).h
            u64 s0 = 0ULL, s1 = 0ULL, s2v = 0ULL, s3 = 0ULL;
            u64 q0 = 0ULL, q1 = 0ULL, q2v = 0ULL, q3 = 0ULL;
            #pragma unroll
            for (int jp2 = 0; jp2 < 5; jp2++) {
                ulonglong2 wc = wcsv[jp2];
                ulonglong2 uu = u2v[jp2];
                s0 = fma2(a0[2*jp2+0], wc.x, s0);  s0 = fma2(a0[2*jp2+1], wc.y, s0);
                s1 = fma2(a1[2*jp2+0], wc.x, s1);  s1 = fma2(a1[2*jp2+1], wc.y, s1);
                s2v= fma2(a2[2*jp2+0], wc.x, s2v); s2v= fma2(a2[2*jp2+1], wc.y, s2v);
                s3 = fma2(a3[2*jp2+0], wc.x, s3);  s3 = fma2(a3[2*jp2+1], wc.y, s3);
                q0 = fma2(a0[2*jp2+0], uu.x, q0);  q0 = fma2(a0[2*jp2+1], uu.y, q0);
                q1 = fma2(a1[2*jp2+0], uu.x, q1);  q1 = fma2(a1[2*jp2+1], uu.y, q1);
                q2v= fma2(a2[2*jp2+0], uu.x, q2v); q2v= fma2(a2[2*jp2+1], uu.y, q2v);
                q3 = fma2(a3[2*jp2+0], uu.x, q3);  q3 = fma2(a3[2*jp2+1], uu.y, q3);
            }

            // quadratic: Q += sum_i h_i * (T h)_i, T upper-tri
            float qs0 = 0.0f, qs1 = 0.0f, qs2 = 0.0f, qs3 = 0.0f;
            #pragma unroll
            for (int i = 0; i < DD; i++) {
                const int kp0 = i >> 1;
                const u64* Trow = (const u64*)(sTf + i * DD);
                u64 y0 = 0ULL, y1 = 0ULL, y2 = 0ULL, y3 = 0ULL;
                #pragma unroll
                for (int kp = kp0; kp < DD/2; kp++) {
                    u64 w = Trow[kp];
                    y0 = fma2(a0[kp], w, y0);
                    y1 = fma2(a1[kp], w, y1);
                    y2 = fma2(a2[kp], w, y2);
                    y3 = fma2(a3[kp], w, y3);
                }
                float lo, hi, hl, hh, h;
                upk(y0, lo, hi); upk(a0[kp0], hl, hh); h = (i & 1) ? hh : hl;
                qs0 = fmaf(h, lo + hi, qs0);
                upk(y1, lo, hi); upk(a1[kp0], hl, hh); h = (i & 1) ? hh : hl;
                qs1 = fmaf(h, lo + hi, qs1);
                upk(y2, lo, hi); upk(a2[kp0], hl, hh); h = (i & 1) ? hh : hl;
                qs2 = fmaf(h, lo + hi, qs2);
                upk(y3, lo, hi); upk(a3[kp0], hl, hh); h = (i & 1) ? hh : hl;
                qs3 = fmaf(h, lo + hi, qs3);
            }

            float lo, hi;
            upk(s0, lo, hi); sl += lo + hi;
            upk(s1, lo, hi); sl += lo + hi;
            upk(s2v, lo, hi); sl += lo + hi;
            upk(s3, lo, hi); sl += lo + hi;
            upk(q0, lo, hi); ql += lo + hi + qs0;
            upk(q1, lo, hi); ql += lo + hi + qs1;
            upk(q2v, lo, hi); ql += lo + hi + qs2;
            upk(q3, lo, hi); ql += lo + hi + qs3;
        } else if (row0 < rowsTotal) {
            // scalar tail
            for (long long r = row0; r < rowsTotal && r < row0 + 4; r++) {
                const float* xr = x + r * DD;
                float h[DD];
                #pragma unroll
                for (int j = 0; j < DD; j++) h[j] = sc1f[j];
                for (int k = 0; k < DD; k++) {
                    float xv = xr[k];
                    #pragma unroll
                    for (int j = 0; j < DD; j++) h[j] = fmaf(xv, sM1f[k * DD + j], h[j]);
                }
                #pragma unroll
                for (int j = 0; j < DD; j++) h[j] = fmaxf(h[j], 0.0f);
                #pragma unroll
                for (int k = 0; k < DD; k++) {
                    sl = fmaf(h[k], swcsf[k], sl);
                    ql = fmaf(h[k], su2f[k], ql);
                }
                for (int i = 0; i < DD; i++) {
                    float y = 0.0f;
                    for (int k = i; k < DD; k++) y = fmaf(h[k], sTf[i * DD + k], y);
                    ql = fmaf(h[i], y, ql);
                }
            }
        }
    }

    // ---- deterministic block reduction ----
    redS[tid] = (double)sl;
    redQ[tid] = (double)ql;
    __syncthreads();
    for (int s = TPB / 2; s > 0; s >>= 1) {
        if (tid < s) { redS[tid] += redS[tid + s]; redQ[tid] += redQ[tid + s]; }
        __syncthreads();
    }
    if (tid == 0) {
        g_pS[blockIdx.x] = redS[0];
        g_pQ[blockIdx.x] = redQ[0];
        __threadfence();
        unsigned int t = atomicAdd(&g_ticket, 1u);
        sIsLast = (t == (unsigned int)(GRID - 1)) ? 1 : 0;
    }
    __syncthreads();

    // ---- last block: global reduce + scalar postlude ----
    if (sIsLast) {
        __threadfence();
        double s = 0.0, q = 0.0;
        for (int i = tid; i < GRID; i += TPB) { s += g_pS[i]; q += g_pQ[i]; }
        redS[tid] = s; redQ[tid] = q;
        __syncthreads();
        for (int st = TPB / 2; st > 0; st >>= 1) {
            if (tid < st) { redS[tid] += redS[tid + st]; redQ[tid] += redQ[tid + st]; }
            __syncthreads();
        }
        if (tid == 0) {
            double sb = 0.0, bb = 0.0;
            #pragma unroll
            for (int m = 0; m < DD; m++) { sb += (double)sbf[m]; bb += (double)sbf[m] * (double)sbf[m]; }
            double S = redS[0] + (double)B * sb;
            double Q = redQ[0] + (double)B * bb;
            float n = (float)sqrt(Q);
            int k = 0;
            while (n > 1.0f && k < 300) { n *= 0.5f; k++; }   // exact halvings in fp32
            float mult = (n < 0.8f) ? 10.0f : 1.0f;
            double scale = ldexp(1.0, -k);
            out[0] = (float)(S * scale * (double)mult);
            g_ticket = 0;
        }
    }
}

// ---------------- entry point ----------------
extern "C" void kernel_launch(void* const* d_in, const int* in_sizes, int n_in,
                              void* d_out, int out_size) {
    const float* x = (const float*)d_in[0];
    const float* W = (const float*)d_in[1];
    const float* b = (const float*)d_in[2];
    const float* R = (const float*)d_in[3];
    int B = in_sizes[0] / DD;

    main_kernel<<<GRID, TPB>>>(x, W, b, R, (float*)d_out, B);
}

// round 10
// speedup vs baseline: 1.4514x; 1.2504x over previous
#include <cuda_runtime.h>
#include <math.h>
#include <stdint.h>

#define DD    20
#define TPB   128
#define GRID  296                    // 2 blocks/SM * 148 SMs
#define TILE_ROWS   512              // 4 rows/thread * 128 threads
#define TILE_FLOATS (TILE_ROWS * DD) // 10240 floats = 40KB
#define DYN_SMEM    (2 * TILE_FLOATS * 4)

typedef unsigned long long u64;

// ---------------- packed f32x2 helpers (sm_103a) ----------------
__device__ __forceinline__ u64 pk(float lo, float hi) {
    u64 r; asm("mov.b64 %0, {%1, %2};" : "=l"(r) : "f"(lo), "f"(hi)); return r;
}
__device__ __forceinline__ void upk(u64 v, float& lo, float& hi) {
    asm("mov.b64 {%0, %1}, %2;" : "=f"(lo), "=f"(hi) : "l"(v));
}
__device__ __forceinline__ u64 fma2(u64 a, u64 b, u64 c) {
    u64 d; asm("fma.rn.f32x2 %0, %1, %2, %3;" : "=l"(d) : "l"(a), "l"(b), "l"(c)); return d;
}
__device__ __forceinline__ u64 relu2(u64 v) {
    float a, b; upk(v, a, b);
    return pk(fmaxf(a, 0.0f), fmaxf(b, 0.0f));
}
__device__ __forceinline__ float comp(const float4& q, int c) {
    return c == 0 ? q.x : c == 1 ? q.y : c == 2 ? q.z : q.w;
}
__device__ __forceinline__ uint32_t smem_u32(const void* p) {
    return (uint32_t)__cvta_generic_to_shared(p);
}
__device__ __forceinline__ void cp_async16(uint32_t dst, const void* src) {
    asm volatile("cp.async.cg.shared.global [%0], [%1], 16;" :: "r"(dst), "l"(src) : "memory");
}

// ---------------- device-global scratch ----------------
__device__ double g_pS[512];
__device__ double g_pQ[512];
__device__ unsigned int g_ticket = 0;

// =====================================================================
// fused persistent kernel: cp.async-staged coalesced x, double buffer,
// 4 rows/thread j-pair packed f32x2 math, last-block finalize
// =====================================================================
__global__ void __launch_bounds__(TPB)
main_kernel(const float* __restrict__ x,
            const float* __restrict__ W,
            const float* __restrict__ b,
            const float* __restrict__ R,
            float* __restrict__ out,
            int B) {
    extern __shared__ __align__(16) float dyn[];   // 2 x-tile buffers
    __shared__ __align__(16) float sM1f[DD * DD];  // M1[k][j]
    __shared__ __align__(16) float sTf[DD * DD];   // T[i][k]: G diag / 2G upper / 0 lower
    __shared__ __align__(16) float sc1f[DD];       // b@R + 1
    __shared__ __align__(16) float swcsf[DD];      // col sums of W
    __shared__ __align__(16) float su2f[DD];       // 2 * W^T b
    __shared__ float sbf[DD];
    __shared__ double redS[TPB];
    __shared__ double redQ[TPB];
    __shared__ int sIsLast;

    const int tid = threadIdx.x;

    // ---- stage W, R into dyn (reused before x pipeline starts) ----
    float* stW = dyn;            // 400 floats
    float* stR = dyn + DD * DD;  // 400 floats
    for (int i = tid; i < DD * DD; i += TPB) { stW[i] = W[i]; stR[i] = R[i]; }
    if (tid < DD) sbf[tid] = b[tid];
    __syncthreads();

    // ---- fold (once per block) ----
    for (int i = tid; i < DD * DD; i += TPB) {
        int k = i / DD, j = i % DD;
        float m1 = 0.0f, g = 0.0f;
        #pragma unroll
        for (int m = 0; m < DD; m++) {
            m1 = fmaf(stW[m * DD + k], stR[m * DD + j], m1);
            g  = fmaf(stW[m * DD + k], stW[m * DD + j], g);
        }
        sM1f[i] = m1;
        sTf[i]  = (j > k) ? (2.0f * g) : ((j == k) ? g : 0.0f);
    }
    if (tid < DD) {
        float c = 1.0f, wcs = 0.0f, u = 0.0f;
        #pragma unroll
        for (int m = 0; m < DD; m++) {
            c   = fmaf(sbf[m], stR[m * DD + tid], c);
            wcs += stW[m * DD + tid];
            u   = fmaf(stW[m * DD + tid], sbf[m], u);
        }
        sc1f[tid]  = c;
        swcsf[tid] = wcs;
        su2f[tid]  = 2.0f * u;
    }
    __syncthreads();   // fold results ready; dyn free for x buffers

    const ulonglong2* sM1v = (const ulonglong2*)sM1f;
    const u64*        sc1v = (const u64*)sc1f;
    const ulonglong2* wcsv = (const ulonglong2*)swcsf;
    const ulonglong2* u2v  = (const ulonglong2*)su2f;

    const int nTiles = (B + TILE_ROWS - 1) / TILE_ROWS;

    // tile loader: coalesced cp.async of 20 16B chunks/thread, zero-pad tail
    auto load_tile = [&](float* buf, int ti) {
        long long baseF = (long long)ti * TILE_FLOATS;
        int validF = (int)(min((long long)TILE_ROWS, (long long)B - (long long)ti * TILE_ROWS)) * DD;
        if (validF == TILE_FLOATS) {
            #pragma unroll
            for (int i = 0; i < 20; i++) {
                int c = tid + TPB * i;
                cp_async16(smem_u32(buf + c * 4), x + baseF + (long long)c * 4);
            }
        } else {
            #pragma unroll
            for (int i = 0; i < 20; i++) {
                int c = tid + TPB * i;
                int s = c * 4;
                if (s + 4 <= validF) {
                    cp_async16(smem_u32(buf + s), x + baseF + s);
                } else {
                    float4 v = make_float4(0.f, 0.f, 0.f, 0.f);
                    if (s + 0 < validF) v.x = x[baseF + s + 0];
                    if (s + 1 < validF) v.y = x[baseF + s + 1];
                    if (s + 2 < validF) v.z = x[baseF + s + 2];
                    if (s + 3 < validF) v.w = x[baseF + s + 3];
                    *(float4*)(buf + s) = v;
                }
            }
        }
    };

    float* xb0 = dyn;
    float* xb1 = dyn + TILE_FLOATS;

    // prologue
    if (blockIdx.x < nTiles) {
        load_tile(xb0, blockIdx.x);
        asm volatile("cp.async.commit_group;" ::: "memory");
    }

    float sl = 0.0f, ql = 0.0f;
    int cur = 0;

    for (int ti = blockIdx.x; ti < nTiles; ti += GRID) {
        int nxt = ti + GRID;
        if (nxt < nTiles) {
            load_tile(cur ? xb0 : xb1, nxt);
            asm volatile("cp.async.commit_group;" ::: "memory");
            asm volatile("cp.async.wait_group 1;" ::: "memory");
        } else {
            asm volatile("cp.async.wait_group 0;" ::: "memory");
        }
        __syncthreads();   // all threads' copies of current tile visible

        const float* xs = cur ? xb1 : xb0;
        // rows: tid, tid+128, tid+256, tid+384 (conflict-free LDS phases)
        const float4* r0 = (const float4*)(xs + (tid          ) * DD);
        const float4* r1 = (const float4*)(xs + (tid + 128    ) * DD);
        const float4* r2 = (const float4*)(xs + (tid + 256    ) * DD);
        const float4* r3 = (const float4*)(xs + (tid + 384    ) * DD);

        u64 a0[DD/2], a1[DD/2], a2[DD/2], a3[DD/2];
        #pragma unroll
        for (int jp = 0; jp < DD/2; jp++) {
            u64 c = sc1v[jp];
            a0[jp] = c; a1[jp] = c; a2[jp] = c; a3[jp] = c;
        }

        #pragma unroll
        for (int i = 0; i < 5; i++) {
            float4 A0 = r0[i], B0 = r1[i], C0 = r2[i], D0 = r3[i];
            #pragma unroll
            for (int c = 0; c < 4; c++) {
                const int k = 4 * i + c;
                float x0 = comp(A0,c), x1 = comp(B0,c), x2 = comp(C0,c), x3 = comp(D0,c);
                u64 xv0 = pk(x0, x0), xv1 = pk(x1, x1), xv2 = pk(x2, x2), xv3 = pk(x3, x3);
                #pragma unroll
                for (int jp2 = 0; jp2 < 5; jp2++) {
                    ulonglong2 w = sM1v[k * 5 + jp2];
                    a0[2*jp2+0] = fma2(xv0, w.x, a0[2*jp2+0]);
                    a1[2*jp2+0] = fma2(xv1, w.x, a1[2*jp2+0]);
                    a2[2*jp2+0] = fma2(xv2, w.x, a2[2*jp2+0]);
                    a3[2*jp2+0] = fma2(xv3, w.x, a3[2*jp2+0]);
                    a0[2*jp2+1] = fma2(xv0, w.y, a0[2*jp2+1]);
                    a1[2*jp2+1] = fma2(xv1, w.y, a1[2*jp2+1]);
                    a2[2*jp2+1] = fma2(xv2, w.y, a2[2*jp2+1]);
                    a3[2*jp2+1] = fma2(xv3, w.y, a3[2*jp2+1]);
                }
            }
        }
        #pragma unroll
        for (int jp = 0; jp < DD/2; jp++) {
            a0[jp] = relu2(a0[jp]); a1[jp] = relu2(a1[jp]);
            a2[jp] = relu2(a2[jp]); a3[jp] = relu2(a3[jp]);
        }

        // linear terms
        u64 s0 = 0ULL, s1 = 0ULL, s2v = 0ULL, s3 = 0ULL;
        u64 q0 = 0ULL, q1 = 0ULL, q2v = 0ULL, q3 = 0ULL;
        #pragma unroll
        for (int jp2 = 0; jp2 < 5; jp2++) {
            ulonglong2 wc = wcsv[jp2];
            ulonglong2 uu = u2v[jp2];
            s0 = fma2(a0[2*jp2+0], wc.x, s0);  s0 = fma2(a0[2*jp2+1], wc.y, s0);
            s1 = fma2(a1[2*jp2+0], wc.x, s1);  s1 = fma2(a1[2*jp2+1], wc.y, s1);
            s2v= fma2(a2[2*jp2+0], wc.x, s2v); s2v= fma2(a2[2*jp2+1], wc.y, s2v);
            s3 = fma2(a3[2*jp2+0], wc.x, s3);  s3 = fma2(a3[2*jp2+1], wc.y, s3);
            q0 = fma2(a0[2*jp2+0], uu.x, q0);  q0 = fma2(a0[2*jp2+1], uu.y, q0);
            q1 = fma2(a1[2*jp2+0], uu.x, q1);  q1 = fma2(a1[2*jp2+1], uu.y, q1);
            q2v= fma2(a2[2*jp2+0], uu.x, q2v); q2v= fma2(a2[2*jp2+1], uu.y, q2v);
            q3 = fma2(a3[2*jp2+0], uu.x, q3);  q3 = fma2(a3[2*jp2+1], uu.y, q3);
        }

        // quadratic: h^T G h via upper-tri T
        float qs0 = 0.0f, qs1 = 0.0f, qs2 = 0.0f, qs3 = 0.0f;
        #pragma unroll
        for (int i = 0; i < DD; i++) {
            const int kp0 = i >> 1;
            const u64* Trow = (const u64*)(sTf + i * DD);
            u64 y0 = 0ULL, y1 = 0ULL, y2 = 0ULL, y3 = 0ULL;
            #pragma unroll
            for (int kp = kp0; kp < DD/2; kp++) {
                u64 w = Trow[kp];
                y0 = fma2(a0[kp], w, y0);
                y1 = fma2(a1[kp], w, y1);
                y2 = fma2(a2[kp], w, y2);
                y3 = fma2(a3[kp], w, y3);
            }
            float lo, hi, hl, hh, h;
            upk(y0, lo, hi); upk(a0[kp0], hl, hh); h = (i & 1) ? hh : hl;
            qs0 = fmaf(h, lo + hi, qs0);
            upk(y1, lo, hi); upk(a1[kp0], hl, hh); h = (i & 1) ? hh : hl;
            qs1 = fmaf(h, lo + hi, qs1);
            upk(y2, lo, hi); upk(a2[kp0], hl, hh); h = (i & 1) ? hh : hl;
            qs2 = fmaf(h, lo + hi, qs2);
            upk(y3, lo, hi); upk(a3[kp0], hl, hh); h = (i & 1) ? hh : hl;
            qs3 = fmaf(h, lo + hi, qs3);
        }

        float lo, hi;
        upk(s0, lo, hi); sl += lo + hi;
        upk(s1, lo, hi); sl += lo + hi;
        upk(s2v, lo, hi); sl += lo + hi;
        upk(s3, lo, hi); sl += lo + hi;
        upk(q0, lo, hi); ql += lo + hi + qs0;
        upk(q1, lo, hi); ql += lo + hi + qs1;
        upk(q2v, lo, hi); ql += lo + hi + qs2;
        upk(q3, lo, hi); ql += lo + hi + qs3;

        __syncthreads();   // everyone done reading this buffer before refill
        cur ^= 1;
    }

    // ---- deterministic block reduction ----
    redS[tid] = (double)sl;
    redQ[tid] = (double)ql;
    __syncthreads();
    for (int s = TPB / 2; s > 0; s >>= 1) {
        if (tid < s) { redS[tid] += redS[tid + s]; redQ[tid] += redQ[tid + s]; }
        __syncthreads();
    }
    if (tid == 0) {
        g_pS[blockIdx.x] = redS[0];
        g_pQ[blockIdx.x] = redQ[0];
        __threadfence();
        unsigned int t = atomicAdd(&g_ticket, 1u);
        sIsLast = (t == (unsigned int)(GRID - 1)) ? 1 : 0;
    }
    __syncthreads();

    // ---- last block: global reduce + padded-row correction + postlude ----
    if (sIsLast) {
        __threadfence();
        double s = 0.0, q = 0.0;
        for (int i = tid; i < GRID; i += TPB) { s += g_pS[i]; q += g_pQ[i]; }
        redS[tid] = s; redQ[tid] = q;
        __syncthreads();
        for (int st = TPB / 2; st > 0; st >>= 1) {
            if (tid < st) { redS[tid] += redS[tid + st]; redQ[tid] += redQ[tid + st]; }
            __syncthreads();
        }
        if (tid == 0) {
            // contribution of one zero-padded row (x = 0): h0 = relu(c1)
            // computed in the SAME fp32 pipeline semantics, accumulated in double
            float h0[DD];
            #pragma unroll
            for (int j = 0; j < DD; j++) h0[j] = fmaxf(sc1f[j], 0.0f);
            float s0f = 0.0f, q0f = 0.0f;
            #pragma unroll
            for (int k = 0; k < DD; k++) {
                s0f = fmaf(h0[k], swcsf[k], s0f);
                q0f = fmaf(h0[k], su2f[k], q0f);
            }
            #pragma unroll
            for (int i = 0; i < DD; i++) {
                float y = 0.0f;
                #pragma unroll
                for (int k = 0; k < DD; k++) y = fmaf(h0[k], sTf[i * DD + k], y);
                q0f = fmaf(h0[i], y, q0f);
            }
            long long nT   = ((long long)B + TILE_ROWS - 1) / TILE_ROWS;
            double  n_inv  = (double)(nT * TILE_ROWS - (long long)B);

            double sb = 0.0, bb = 0.0;
            #pragma unroll
            for (int m = 0; m < DD; m++) { sb += (double)sbf[m]; bb += (double)sbf[m] * (double)sbf[m]; }

            double S = redS[0] - n_inv * (double)s0f + (double)B * sb;
            double Q = redQ[0] - n_inv * (double)q0f + (double)B * bb;
            float n = (float)sqrt(Q);
            int k = 0;
            while (n > 1.0f && k < 300) { n *= 0.5f; k++; }   // exact halvings in fp32
            float mult = (n < 0.8f) ? 10.0f : 1.0f;
            double scale = ldexp(1.0, -k);
            out[0] = (float)(S * scale * (double)mult);
            g_ticket = 0;
        }
    }
}

// ---------------- entry point ----------------
extern "C" void kernel_launch(void* const* d_in, const int* in_sizes, int n_in,
                              void* d_out, int out_size) {
    const float* x = (const float*)d_in[0];
    const float* W = (const float*)d_in[1];
    const float* b = (const float*)d_in[2];
    const float* R = (const float*)d_in[3];
    int B = in_sizes[0] / DD;

    cudaFuncSetAttribute(main_kernel, cudaFuncAttributeMaxDynamicSharedMemorySize, DYN_SMEM);
    main_kernel<<<GRID, TPB, DYN_SMEM>>>(x, W, b, R, (float*)d_out, B);
}